// round 2
// baseline (speedup 1.0000x reference)
#include <cuda_runtime.h>

// Problem constants (fixed shapes from reference: x[32,3,512,512] fp32)
#define NB        32
#define HW        262144            // 512*512
#define NBINS     256
#define F4_PER_B  (HW / 4)          // 65536 float4 groups per channel plane
#define BLK_PER_B 64
#define THREADS   256
#define NUM_PIXEL 262400.0f         // H*W + 256

// Scratch: per-batch integer histograms. __device__ global (no allocation).
__device__ int g_hist[NB][NBINS];

__global__ void zero_hist_kernel() {
    int i = blockIdx.x * blockDim.x + threadIdx.x;
    if (i < NB * NBINS) ((int*)g_hist)[i] = 0;
}

__device__ __forceinline__ void bin4(int* sh, float4 a, float4 c, float4 d) {
    const float s = 255.0f / 3.0f;
    int i0 = (int)((a.x + c.x + d.x) * s);
    int i1 = (int)((a.y + c.y + d.y) * s);
    int i2 = (int)((a.z + c.z + d.z) * s);
    int i3 = (int)((a.w + c.w + d.w) * s);
    i0 = min(max(i0, 0), 255);
    i1 = min(max(i1, 0), 255);
    i2 = min(max(i2, 0), 255);
    i3 = min(max(i3, 0), 255);
    atomicAdd(&sh[i0], 1);
    atomicAdd(&sh[i1], 1);
    atomicAdd(&sh[i2], 1);
    atomicAdd(&sh[i3], 1);
}

__global__ void __launch_bounds__(THREADS) hist_kernel(const float* __restrict__ x) {
    __shared__ int sh[NBINS];
    const int b = blockIdx.y;

    for (int i = threadIdx.x; i < NBINS; i += THREADS) sh[i] = 0;
    __syncthreads();

    // Channel planes for this batch: contiguous, HW floats apart.
    const float4* __restrict__ p0 = (const float4*)(x + (size_t)b * 3 * HW);
    const float4* __restrict__ p1 = p0 + F4_PER_B;
    const float4* __restrict__ p2 = p1 + F4_PER_B;

    const int stride = BLK_PER_B * THREADS;          // 16384
    // F4_PER_B / stride = 4 trips; unroll 2 -> 2 outer iterations, 6 LDG.128
    // in flight per trip for latency hiding.
    int i = blockIdx.x * THREADS + threadIdx.x;
    #pragma unroll
    for (int t = 0; t < F4_PER_B / (2 * stride); t++) {
        int j = i + stride;
        float4 a0 = p0[i], c0 = p1[i], d0 = p2[i];
        float4 a1 = p0[j], c1 = p1[j], d1 = p2[j];
        bin4(sh, a0, c0, d0);
        bin4(sh, a1, c1, d1);
        i += 2 * stride;
    }
    __syncthreads();

    for (int k = threadIdx.x; k < NBINS; k += THREADS) {
        int v = sh[k];
        if (v) atomicAdd(&g_hist[b][k], v);
    }
}

__global__ void entropy_kernel(float* __restrict__ out) {
    __shared__ float red[THREADS];
    const int t = threadIdx.x;

    const float inv = 1.0f / NUM_PIXEL;
    float acc = 0.0f;

    // Thread t owns bin t across all 32 batches.
    #pragma unroll 4
    for (int b = 0; b < NB; b++) {
        // bin-0 quirk: reference overwrites bin0 count with H*W.
        float cnt = (t == 0) ? (float)HW : (float)g_hist[b][t];
        float p = (cnt + 1.0f) * inv;   // '+1' smoothing
        acc += p * logf(p);
    }
    red[t] = acc;
    __syncthreads();

    #pragma unroll
    for (int sft = THREADS / 2; sft > 0; sft >>= 1) {
        if (t < sft) red[t] += red[t + sft];
        __syncthreads();
    }
    if (t == 0) out[0] = red[0] / (float)NB;
}

extern "C" void kernel_launch(void* const* d_in, const int* in_sizes, int n_in,
                              void* d_out, int out_size) {
    const float* x = (const float*)d_in[0];
    float* out = (float*)d_out;

    zero_hist_kernel<<<(NB * NBINS + THREADS - 1) / THREADS, THREADS>>>();
    hist_kernel<<<dim3(BLK_PER_B, NB), THREADS>>>(x);
    entropy_kernel<<<1, THREADS>>>(out);
}

// round 5
// speedup vs baseline: 1.1223x; 1.1223x over previous
#include <cuda_runtime.h>

// Problem constants (fixed shapes from reference: x[32,3,512,512] fp32)
#define NB        32
#define HW        262144            // 512*512
#define NBINS     256
#define F4_PER_B  (HW / 4)          // 65536 float4 groups per channel plane
#define BLK_PER_B 64
#define THREADS   256
#define NUM_PIXEL 262400.0f         // H*W + 256

// Scratch (no allocation): per-batch integer histograms.
// Contract: zero at hist_kernel entry. First launch: BSS zero. Every replay:
// entropy_kernel zeroed it at the end of the previous launch (stream-ordered).
__device__ int g_hist[NB][NBINS];

__device__ __forceinline__ void bin4(int* sh, float4 a, float4 c, float4 d) {
    const float s = 255.0f / 3.0f;
    int i0 = (int)((a.x + c.x + d.x) * s);
    int i1 = (int)((a.y + c.y + d.y) * s);
    int i2 = (int)((a.z + c.z + d.z) * s);
    int i3 = (int)((a.w + c.w + d.w) * s);
    i0 = min(max(i0, 0), 255);
    i1 = min(max(i1, 0), 255);
    i2 = min(max(i2, 0), 255);
    i3 = min(max(i3, 0), 255);
    atomicAdd(&sh[i0], 1);
    atomicAdd(&sh[i1], 1);
    atomicAdd(&sh[i2], 1);
    atomicAdd(&sh[i3], 1);
}

__global__ void __launch_bounds__(THREADS)
hist_kernel(const float* __restrict__ x) {
    __shared__ int sh[NBINS];
    const int b = blockIdx.y;
    const int t = threadIdx.x;

    for (int i = t; i < NBINS; i += THREADS) sh[i] = 0;
    __syncthreads();

    // Channel planes for this batch: contiguous, HW floats apart.
    const float4* __restrict__ p0 = (const float4*)(x + (size_t)b * 3 * HW);
    const float4* __restrict__ p1 = p0 + F4_PER_B;
    const float4* __restrict__ p2 = p1 + F4_PER_B;

    const int stride = BLK_PER_B * THREADS;  // 16384
    int i = blockIdx.x * THREADS + t;
    // 4 trips unrolled 2x -> 6 LDG.128 in flight per trip.
    #pragma unroll
    for (int it = 0; it < F4_PER_B / (2 * stride); it++) {
        int j = i + stride;
        float4 a0 = p0[i], c0 = p1[i], d0 = p2[i];
        float4 a1 = p0[j], c1 = p1[j], d1 = p2[j];
        bin4(sh, a0, c0, d0);
        bin4(sh, a1, c1, d1);
        i += 2 * stride;
    }
    __syncthreads();

    for (int k = t; k < NBINS; k += THREADS) {
        int v = sh[k];
        if (v) atomicAdd(&g_hist[b][k], v);
    }
}

__global__ void entropy_kernel(float* __restrict__ out) {
    __shared__ float red[THREADS];
    const int t = threadIdx.x;

    const float inv = 1.0f / NUM_PIXEL;
    float acc = 0.0f;

    // Thread t owns bin t across all 32 batches.
    #pragma unroll 4
    for (int b = 0; b < NB; b++) {
        // bin-0 quirk: reference overwrites bin0 count with H*W.
        float cnt = (t == 0) ? (float)HW : (float)g_hist[b][t];
        float p = (cnt + 1.0f) * inv;   // '+1' smoothing
        acc += p * logf(p);
    }
    red[t] = acc;
    __syncthreads();

    #pragma unroll
    for (int sft = THREADS / 2; sft > 0; sft >>= 1) {
        if (t < sft) red[t] += red[t + sft];
        __syncthreads();
    }
    if (t == 0) out[0] = red[0] / (float)NB;

    // Cleanup for the next graph replay: zero g_hist (32*256 ints, 256 thr).
    __syncthreads();
    for (int k = t; k < NB * NBINS; k += THREADS) ((int*)g_hist)[k] = 0;
}

extern "C" void kernel_launch(void* const* d_in, const int* in_sizes, int n_in,
                              void* d_out, int out_size) {
    const float* x = (const float*)d_in[0];
    float* out = (float*)d_out;

    hist_kernel<<<dim3(BLK_PER_B, NB), THREADS>>>(x);
    entropy_kernel<<<1, THREADS>>>(out);
}

// round 7
// speedup vs baseline: 1.2144x; 1.0821x over previous
#include <cuda_runtime.h>

// Problem constants (fixed shapes from reference: x[32,3,512,512] fp32)
#define NB        32
#define HW        262144            // 512*512
#define NBINS     256
#define F4_PER_B  (HW / 4)          // 65536 float4 groups per channel plane
#define BLK_PER_B 64
#define THREADS   256
#define NUM_PIXEL 262400.0f         // H*W + 256

// Scratch (no allocation): per-batch integer histograms.
// Contract: zero at hist_kernel entry. First launch: BSS zero. Every replay:
// entropy_kernel zeroes each slot right after reading it (stream-ordered).
__device__ int g_hist[NB][NBINS];

__device__ __forceinline__ void bin4(int* sh, float4 a, float4 c, float4 d) {
    const float s = 255.0f / 3.0f;
    int i0 = (int)((a.x + c.x + d.x) * s);
    int i1 = (int)((a.y + c.y + d.y) * s);
    int i2 = (int)((a.z + c.z + d.z) * s);
    int i3 = (int)((a.w + c.w + d.w) * s);
    i0 = min(max(i0, 0), 255);
    i1 = min(max(i1, 0), 255);
    i2 = min(max(i2, 0), 255);
    i3 = min(max(i3, 0), 255);
    atomicAdd(&sh[i0], 1);
    atomicAdd(&sh[i1], 1);
    atomicAdd(&sh[i2], 1);
    atomicAdd(&sh[i3], 1);
}

__global__ void __launch_bounds__(THREADS)
hist_kernel(const float* __restrict__ x) {
    __shared__ int sh[NBINS];
    const int b = blockIdx.y;
    const int t = threadIdx.x;

    for (int i = t; i < NBINS; i += THREADS) sh[i] = 0;
    __syncthreads();

    // Channel planes for this batch: contiguous, HW floats apart.
    const float4* __restrict__ p0 = (const float4*)(x + (size_t)b * 3 * HW);
    const float4* __restrict__ p1 = p0 + F4_PER_B;
    const float4* __restrict__ p2 = p1 + F4_PER_B;

    const int stride = BLK_PER_B * THREADS;  // 16384
    int i = blockIdx.x * THREADS + t;
    // 4 trips unrolled 2x -> 6 LDG.128 in flight per trip.
    #pragma unroll
    for (int it = 0; it < F4_PER_B / (2 * stride); it++) {
        int j = i + stride;
        float4 a0 = p0[i], c0 = p1[i], d0 = p2[i];
        float4 a1 = p0[j], c1 = p1[j], d1 = p2[j];
        bin4(sh, a0, c0, d0);
        bin4(sh, a1, c1, d1);
        i += 2 * stride;
    }
    __syncthreads();

    for (int k = t; k < NBINS; k += THREADS) {
        int v = sh[k];
        if (v) atomicAdd(&g_hist[b][k], v);
    }
}

__global__ void __launch_bounds__(THREADS)
entropy_kernel(float* __restrict__ out) {
    __shared__ float warp_sum[THREADS / 32];
    const int t = threadIdx.x;

    const float inv = 1.0f / NUM_PIXEL;
    float acc = 0.0f;

    // Thread t owns bin t across all 32 batches. unroll 8 -> MLP~8 coalesced
    // loads in flight (covers L2 latency) without register blowup.
    // Each slot is zeroed immediately after reading -> no separate cleanup.
    #pragma unroll 8
    for (int b = 0; b < NB; b++) {
        int raw = g_hist[b][t];
        g_hist[b][t] = 0;
        // bin-0 quirk: reference overwrites bin0 count with H*W.
        float cnt = (t == 0) ? (float)HW : (float)raw;
        float p = (cnt + 1.0f) * inv;     // '+1' smoothing
        acc += p * __logf(p);             // MUFU LG2 path; err ~1e-6 rel
    }

    // Warp reduce, then 8 leaders reduce in warp 0.
    #pragma unroll
    for (int m = 16; m > 0; m >>= 1)
        acc += __shfl_xor_sync(0xFFFFFFFF, acc, m);
    if ((t & 31) == 0) warp_sum[t >> 5] = acc;
    __syncthreads();
    if (t < 32) {
        float v = (t < THREADS / 32) ? warp_sum[t] : 0.0f;
        #pragma unroll
        for (int m = 4; m > 0; m >>= 1)
            v += __shfl_xor_sync(0xFFFFFFFF, v, m);
        if (t == 0) out[0] = v / (float)NB;
    }
}

extern "C" void kernel_launch(void* const* d_in, const int* in_sizes, int n_in,
                              void* d_out, int out_size) {
    const float* x = (const float*)d_in[0];
    float* out = (float*)d_out;

    hist_kernel<<<dim3(BLK_PER_B, NB), THREADS>>>(x);
    entropy_kernel<<<1, THREADS>>>(out);
}

// round 9
// speedup vs baseline: 1.2478x; 1.0275x over previous
#include <cuda_runtime.h>

// Problem constants (fixed shapes from reference: x[32,3,512,512] fp32)
#define NB        32
#define HW        262144            // 512*512
#define NBINS     256
#define F4_PER_B  (HW / 4)          // 65536 float4 groups per channel plane
#define BLK_PER_B 64
#define THREADS   256
#define NUM_PIXEL 262400.0f         // H*W + 256

// Scratch (no allocation): per-batch integer histograms.
// Contract: zero at hist_kernel entry. First launch: BSS zero. Every replay:
// entropy_kernel zeroes each slot right after reading it (stream-ordered).
__device__ int g_hist[NB][NBINS];

__device__ __forceinline__ void bin4(int* sh, float4 a, float4 c, float4 d) {
    const float s = 255.0f / 3.0f;
    int i0 = (int)((a.x + c.x + d.x) * s);
    int i1 = (int)((a.y + c.y + d.y) * s);
    int i2 = (int)((a.z + c.z + d.z) * s);
    int i3 = (int)((a.w + c.w + d.w) * s);
    i0 = min(max(i0, 0), 255);
    i1 = min(max(i1, 0), 255);
    i2 = min(max(i2, 0), 255);
    i3 = min(max(i3, 0), 255);
    atomicAdd(&sh[i0], 1);
    atomicAdd(&sh[i1], 1);
    atomicAdd(&sh[i2], 1);
    atomicAdd(&sh[i3], 1);
}

__global__ void __launch_bounds__(THREADS)
hist_kernel(const float* __restrict__ x, float* __restrict__ out) {
    __shared__ int sh[NBINS];
    const int b = blockIdx.y;
    const int t = threadIdx.x;

    // Zero the accumulator for this launch (sole writer; entropy_kernel runs
    // stream-after, so no race). d_out is poisoned pre-timing -> must init.
    if (blockIdx.x == 0 && b == 0 && t == 0) out[0] = 0.0f;

    for (int i = t; i < NBINS; i += THREADS) sh[i] = 0;
    __syncthreads();

    // Channel planes for this batch: contiguous, HW floats apart.
    const float4* __restrict__ p0 = (const float4*)(x + (size_t)b * 3 * HW);
    const float4* __restrict__ p1 = p0 + F4_PER_B;
    const float4* __restrict__ p2 = p1 + F4_PER_B;

    const int stride = BLK_PER_B * THREADS;  // 16384
    int i = blockIdx.x * THREADS + t;
    // 4 trips unrolled 2x -> 6 LDG.128 in flight per trip.
    #pragma unroll
    for (int it = 0; it < F4_PER_B / (2 * stride); it++) {
        int j = i + stride;
        float4 a0 = p0[i], c0 = p1[i], d0 = p2[i];
        float4 a1 = p0[j], c1 = p1[j], d1 = p2[j];
        bin4(sh, a0, c0, d0);
        bin4(sh, a1, c1, d1);
        i += 2 * stride;
    }
    __syncthreads();

    for (int k = t; k < NBINS; k += THREADS) {
        int v = sh[k];
        if (v) atomicAdd(&g_hist[b][k], v);
    }
}

// One block per batch: block b reads its 256-bin row (one coalesced 1KB
// burst), zeros it for the next replay, computes sum(p*log p), and
// accumulates partial/NB into out[0].
__global__ void __launch_bounds__(THREADS)
entropy_kernel(float* __restrict__ out) {
    __shared__ float warp_sum[THREADS / 32];
    const int b = blockIdx.x;
    const int t = threadIdx.x;

    const float inv = 1.0f / NUM_PIXEL;

    int raw = g_hist[b][t];
    g_hist[b][t] = 0;                      // cleanup for next replay
    // bin-0 quirk: reference overwrites bin0 count with H*W.
    float cnt = (t == 0) ? (float)HW : (float)raw;
    float p = (cnt + 1.0f) * inv;          // '+1' smoothing
    float acc = p * __logf(p);             // MUFU LG2 path; ~1e-6 rel err

    #pragma unroll
    for (int m = 16; m > 0; m >>= 1)
        acc += __shfl_xor_sync(0xFFFFFFFF, acc, m);
    if ((t & 31) == 0) warp_sum[t >> 5] = acc;
    __syncthreads();
    if (t < 32) {
        float v = (t < THREADS / 32) ? warp_sum[t] : 0.0f;
        #pragma unroll
        for (int m = 4; m > 0; m >>= 1)
            v += __shfl_xor_sync(0xFFFFFFFF, v, m);
        if (t == 0) atomicAdd(out, v * (1.0f / (float)NB));
    }
}

extern "C" void kernel_launch(void* const* d_in, const int* in_sizes, int n_in,
                              void* d_out, int out_size) {
    const float* x = (const float*)d_in[0];
    float* out = (float*)d_out;

    hist_kernel<<<dim3(BLK_PER_B, NB), THREADS>>>(x, out);
    entropy_kernel<<<NB, THREADS>>>(out);
}